// round 15
// baseline (speedup 1.0000x reference)
#include <cuda_runtime.h>
#include <cuda_fp16.h>
#include <cstdint>

// ============================================================================
// out[4096,4096] = x @ W^T + b  (fp32).
// fp16 warp-MMA GEMM, CTA tile 128x128, split-K=2 with deterministic
// arrive-counter combine (partials in global scratch; last arriver adds).
// 4 warps @ 64x64, 3-stage cp.async ring, 2 CTAs/SM.
// ============================================================================

#define DIM 4096
#define BM 128
#define BN 128
#define BK 64
#define NKT_H 32                // k-tiles per CTA (half of 64)
#define THREADS 128
#define STAGES 3
#define NTILES 1024

// per-stage smem: A 16K | B 16K = 32KB (128B rows, 8x16B chunks, XOR swizzle)
#define STAGE_BYTES 32768
#define OFF_A 0
#define OFF_B 16384
#define SM_BIAS 0               // 128 floats at [0,512)
#define SM_FLAG 512             // combine-role flag at [512,516)
#define SM_TILES 1024
#define SMEM_TOTAL (SM_TILES + STAGES * STAGE_BYTES)   // 99328 (x2 CTAs = 194KB/SM)

// ---------------------------------------------------------------------------
// Scratch: fp16 inputs, fp32 partials, per-tile arrive counters
// ---------------------------------------------------------------------------
__device__ __align__(256) __half g_x[(size_t)DIM * DIM];
__device__ __align__(256) __half g_w[(size_t)DIM * DIM];
__device__ __align__(256) float g_part[(size_t)2 * NTILES * BM * BN];  // 128 MB
__device__ unsigned int g_cnt[NTILES];

// ---------------------------------------------------------------------------
// Helpers
// ---------------------------------------------------------------------------
static __device__ __forceinline__ uint32_t smem_u32(const void* p) {
    uint32_t a;
    asm("{ .reg .u64 t; cvta.to.shared.u64 t, %1; cvt.u32.u64 %0, t; }"
        : "=r"(a) : "l"(p));
    return a;
}

static __device__ __forceinline__ void cp16(uint32_t s, const void* g) {
    asm volatile("cp.async.cg.shared.global [%0], [%1], 16;" :: "r"(s), "l"(g));
}

static __device__ __forceinline__ void ldsm4(uint32_t* r, uint32_t a) {
    asm volatile("ldmatrix.sync.aligned.m8n8.x4.shared.b16 {%0,%1,%2,%3}, [%4];"
                 : "=r"(r[0]), "=r"(r[1]), "=r"(r[2]), "=r"(r[3]) : "r"(a));
}

static __device__ __forceinline__ void mma16816(float* c, const uint32_t* a,
                                                const uint32_t* b) {
    asm volatile(
        "mma.sync.aligned.m16n8k16.row.col.f32.f16.f16.f32 "
        "{%0,%1,%2,%3}, {%4,%5,%6,%7}, {%8,%9}, {%0,%1,%2,%3};"
        : "+f"(c[0]), "+f"(c[1]), "+f"(c[2]), "+f"(c[3])
        : "r"(a[0]), "r"(a[1]), "r"(a[2]), "r"(a[3]), "r"(b[0]), "r"(b[1]));
}

// ---------------------------------------------------------------------------
// Convert kernel: seg 0 -> x fp16, seg 1 -> W fp16. Block 0 zeroes counters.
// ---------------------------------------------------------------------------
__global__ __launch_bounds__(256) void convert_kernel(const float* __restrict__ x,
                                                      const float* __restrict__ W) {
    if (blockIdx.x == 0) {
#pragma unroll
        for (int j = 0; j < 4; ++j)
            g_cnt[threadIdx.x * 4 + j] = 0u;
    }
    const int half_grid = (int)(gridDim.x >> 1);
    const float* src = (blockIdx.x < half_grid) ? x : W;
    __half* dst = (blockIdx.x < half_grid) ? g_x : g_w;
    int blk = (blockIdx.x < half_grid) ? blockIdx.x : (blockIdx.x - half_grid);
    size_t i = ((size_t)blk * blockDim.x + threadIdx.x) * 8;
    float4 v0 = *reinterpret_cast<const float4*>(src + i);
    float4 v1 = *reinterpret_cast<const float4*>(src + i + 4);
    __half2 h[4];
    h[0] = __floats2half2_rn(v0.x, v0.y);
    h[1] = __floats2half2_rn(v0.z, v0.w);
    h[2] = __floats2half2_rn(v1.x, v1.y);
    h[3] = __floats2half2_rn(v1.z, v1.w);
    *reinterpret_cast<uint4*>(dst + i) = *reinterpret_cast<const uint4*>(h);
}

// ---------------------------------------------------------------------------
// Stage loader (128 threads): rows 128B wide (64 halfs); chunk cc of row r at
//   r*128 + ((cc ^ (r&7))<<4)  -> conflict-free for cp.async AND ldmatrix.
// ---------------------------------------------------------------------------
static __device__ __forceinline__ void load_stage(uint32_t sb, int stage, int kt,
                                                  int tm, int tn, int tid) {
    uint32_t st = sb + SM_TILES + stage * STAGE_BYTES;
    const uint32_t k0 = (uint32_t)kt * BK;
#pragma unroll
    for (int i = 0; i < 8; ++i) {          // A: 1024 chunks / 128 thr
        int c = i * 128 + tid;
        int r = c >> 3, cc = c & 7;
        uint32_t so = (uint32_t)r * 128 + (uint32_t)((cc ^ (r & 7)) << 4);
        cp16(st + OFF_A + so, g_x + (size_t)(tm * BM + r) * DIM + k0 + cc * 8);
    }
#pragma unroll
    for (int i = 0; i < 8; ++i) {          // B: 1024 chunks / 128 thr
        int c = i * 128 + tid;
        int r = c >> 3, cc = c & 7;
        uint32_t so = (uint32_t)r * 128 + (uint32_t)((cc ^ (r & 7)) << 4);
        cp16(st + OFF_B + so, g_w + (size_t)(tn * BN + r) * DIM + k0 + cc * 8);
    }
}

// ---------------------------------------------------------------------------
// GEMM: partial D(128x128) over one K-half; arrive-counter combine.
// 4 warps @ 64x64: wm = wid&1 (2 x 64 rows), wn = wid>>1 (2 x 64 cols).
// ---------------------------------------------------------------------------
__global__ __launch_bounds__(THREADS, 2) void gemm_kernel(const float* __restrict__ bias,
                                                          float* __restrict__ out) {
    extern __shared__ __align__(1024) char smem[];
    uint32_t sb = smem_u32(smem);
    const int tid = threadIdx.x;
    const int lane = tid & 31, wid = tid >> 5;
    const int wm = wid & 1, wn = wid >> 1;

    // grid = 2048: kh = pid&1 (pairs adjacent -> co-scheduled), tile = pid>>1
    const int pid = blockIdx.x;
    const int kh = pid & 1;
    const int tile = pid >> 1;
    const int tm = tile & 31;              // 0..31 (fast -> A panel L2-resident)
    const int tn = tile >> 5;              // 0..31
    const int kbase = kh * NKT_H;

    reinterpret_cast<float*>(smem + SM_BIAS)[tid] = bias[tn * BN + tid];

    // per-lane ldmatrix address components (row*128 base + row-swizzle key r&7)
    uint32_t aoff[4], asw[4];
#pragma unroll
    for (int mt = 0; mt < 4; ++mt) {
        int r = wm * 64 + mt * 16 + (lane & 15);
        aoff[mt] = (uint32_t)r * 128;
        asw[mt] = (uint32_t)(r & 7);
    }
    uint32_t boff[4], bsw[4];
#pragma unroll
    for (int jj = 0; jj < 4; ++jj) {
        int r = wn * 64 + jj * 16 + ((lane >> 4) & 1) * 8 + (lane & 7);
        boff[jj] = (uint32_t)r * 128;
        bsw[jj] = (uint32_t)(r & 7);
    }
    const uint32_t cAsel = (uint32_t)(lane >> 4);        // A k-chunk select (0/1)
    const uint32_t cBsel = (uint32_t)((lane >> 3) & 1);  // B k-chunk select (0/1)

    float acc[4][8][4];
#pragma unroll
    for (int mt = 0; mt < 4; ++mt)
#pragma unroll
        for (int nt = 0; nt < 8; ++nt)
#pragma unroll
            for (int k = 0; k < 4; ++k) acc[mt][nt][k] = 0.f;

    // prologue: 2 stages in flight
    load_stage(sb, 0, kbase + 0, tm, tn, tid);
    asm volatile("cp.async.commit_group;");
    load_stage(sb, 1, kbase + 1, tm, tn, tid);
    asm volatile("cp.async.commit_group;");

    // one k-tile body at compile-time stage index; t local to the K half
    auto body = [&](int t, int sc) {
        asm volatile("cp.async.wait_group 1;");
        __syncthreads();

        if (t + 2 < NKT_H) {
            int sld = sc + 2; if (sld >= STAGES) sld -= STAGES;
            load_stage(sb, sld, kbase + t + 2, tm, tn, tid);
        }
        asm volatile("cp.async.commit_group;");   // empty group ok

        const uint32_t stg = sb + SM_TILES + (uint32_t)sc * STAGE_BYTES;
#pragma unroll
        for (int s = 0; s < 4; ++s) {             // four k16 steps per BK=64
            uint32_t a[4][4], b[4][4];
#pragma unroll
            for (int mt = 0; mt < 4; ++mt) {
                uint32_t ca = (uint32_t)(2 * s) + cAsel;
                ldsm4(a[mt], stg + OFF_A + aoff[mt] + ((ca ^ asw[mt]) << 4));
            }
#pragma unroll
            for (int jj = 0; jj < 4; ++jj) {
                uint32_t cb = (uint32_t)(2 * s) + cBsel;
                ldsm4(b[jj], stg + OFF_B + boff[jj] + ((cb ^ bsw[jj]) << 4));
            }
#pragma unroll
            for (int jj = 0; jj < 4; ++jj) {
                const int n0 = 2 * jj, n1 = 2 * jj + 1;
#pragma unroll
                for (int mt = 0; mt < 4; ++mt) {
                    mma16816(acc[mt][n0], a[mt], b[jj]);
                    mma16816(acc[mt][n1], a[mt], b[jj] + 2);
                }
            }
        }
    };

    // 32 k-tiles = 10 x (ring of 3, compile-time stages) + 2 tail
#pragma unroll 1
    for (int tt = 0; tt < NKT_H - 2; tt += 3) {
        body(tt, 0);
        body(tt + 1, 1);
        body(tt + 2, 2);
    }
    body(NKT_H - 2, 0);
    body(NKT_H - 1, 1);

    // ---- epilogue: store partial, arrive; last arriver combines + bias ----
    float* sp = g_part + (size_t)pid * (BM * BN);
#pragma unroll
    for (int mt = 0; mt < 4; ++mt) {
#pragma unroll
        for (int nt = 0; nt < 8; ++nt) {
            int lrow = wm * 64 + mt * 16 + (lane >> 2);
            int lcl = wn * 64 + nt * 8 + 2 * (lane & 3);
            float* q0 = sp + lrow * BN + lcl;
            float* q1 = q0 + 8 * BN;
            *reinterpret_cast<float2*>(q0) = make_float2(acc[mt][nt][0], acc[mt][nt][1]);
            *reinterpret_cast<float2*>(q1) = make_float2(acc[mt][nt][2], acc[mt][nt][3]);
        }
    }
    __threadfence();
    __syncthreads();
    if (tid == 0)
        *reinterpret_cast<unsigned*>(smem + SM_FLAG) = atomicAdd(&g_cnt[tile], 1u);
    __syncthreads();

    if (*reinterpret_cast<unsigned*>(smem + SM_FLAG) == 1u) {
        __threadfence();   // acquire: partner's stores visible (it fenced+arrived)
        const float* pp = g_part + (size_t)(pid ^ 1) * (BM * BN);
        const float* sbias = reinterpret_cast<const float*>(smem + SM_BIAS);
#pragma unroll
        for (int mt = 0; mt < 4; ++mt) {
#pragma unroll
            for (int nt = 0; nt < 8; ++nt) {
                int lrow = wm * 64 + mt * 16 + (lane >> 2);
                int lcl = wn * 64 + nt * 8 + 2 * (lane & 3);
                float2 o0 = *reinterpret_cast<const float2*>(pp + lrow * BN + lcl);
                float2 o1 = *reinterpret_cast<const float2*>(pp + (lrow + 8) * BN + lcl);
                float b0 = sbias[lcl], b1 = sbias[lcl + 1];
                int row = tm * BM + lrow;
                float* p0 = out + (size_t)row * DIM + tn * BN + lcl;
                float* p1 = p0 + 8 * DIM;
                *reinterpret_cast<float2*>(p0) =
                    make_float2(acc[mt][nt][0] + o0.x + b0, acc[mt][nt][1] + o0.y + b1);
                *reinterpret_cast<float2*>(p1) =
                    make_float2(acc[mt][nt][2] + o1.x + b0, acc[mt][nt][3] + o1.y + b1);
            }
        }
    }
}

// ---------------------------------------------------------------------------
// Launch
// ---------------------------------------------------------------------------
extern "C" void kernel_launch(void* const* d_in, const int* in_sizes, int n_in,
                              void* d_out, int out_size) {
    const float* x = (const float*)d_in[0];
    const float* W = (const float*)d_in[1];
    const float* b = (const float*)d_in[2];
    float* out = (float*)d_out;

    // 2 segments x 8192 blocks (block 0 also zeroes the arrive counters)
    convert_kernel<<<16384, 256>>>(x, W);

    cudaFuncSetAttribute(gemm_kernel, cudaFuncAttributeMaxDynamicSharedMemorySize,
                         SMEM_TOTAL);
    // 1024 tiles x 2 K-halves, pairs adjacent
    gemm_kernel<<<2 * NTILES, THREADS, SMEM_TOTAL>>>(b, out);
}

// round 16
// speedup vs baseline: 1.0506x; 1.0506x over previous
#include <cuda_runtime.h>
#include <cuda_fp16.h>
#include <cstdint>

// ============================================================================
// out[4096,4096] = x @ W^T + b  (fp32).
// fp16 warp-MMA GEMM, CTA tile 128x128, 4 warps @ 64x64, 3-stage cp.async
// ring, 2 CTAs/SM. Hybrid split-K: tiles 0..887 full-K (3 perfectly packed
// rounds of 296); tiles 888..1023 split-K=2 (272 CTAs, deterministic
// arrive-counter combine) to fill the final round.
// ============================================================================

#define DIM 4096
#define BM 128
#define BN 128
#define BK 64
#define NKT 64                  // full-K k-tiles
#define NKT_H 32                // split-K k-tiles per CTA
#define THREADS 128
#define STAGES 3
#define FULL_TILES 888
#define SPLIT_TILES 136         // tiles 888..1023
#define GRID_GEMM (FULL_TILES + 2 * SPLIT_TILES)   // 1160

// per-stage smem: A 16K | B 16K = 32KB (128B rows, 8x16B chunks, XOR swizzle)
#define STAGE_BYTES 32768
#define OFF_A 0
#define OFF_B 16384
#define SM_BIAS 0               // 128 floats at [0,512)
#define SM_FLAG 512             // combine-role flag
#define SM_TILES 1024
#define SMEM_TOTAL (SM_TILES + STAGES * STAGE_BYTES)   // 99328 (x2 CTAs = 194KB/SM)

// ---------------------------------------------------------------------------
// Scratch: fp16 inputs, fp32 partials for split tiles, arrive counters
// ---------------------------------------------------------------------------
__device__ __align__(256) __half g_x[(size_t)DIM * DIM];
__device__ __align__(256) __half g_w[(size_t)DIM * DIM];
__device__ __align__(256) float g_part[(size_t)2 * SPLIT_TILES * BM * BN];  // ~18 MB
__device__ unsigned int g_cnt[SPLIT_TILES];

// ---------------------------------------------------------------------------
// Helpers
// ---------------------------------------------------------------------------
static __device__ __forceinline__ uint32_t smem_u32(const void* p) {
    uint32_t a;
    asm("{ .reg .u64 t; cvta.to.shared.u64 t, %1; cvt.u32.u64 %0, t; }"
        : "=r"(a) : "l"(p));
    return a;
}

static __device__ __forceinline__ void cp16(uint32_t s, const void* g) {
    asm volatile("cp.async.cg.shared.global [%0], [%1], 16;" :: "r"(s), "l"(g));
}

static __device__ __forceinline__ void ldsm4(uint32_t* r, uint32_t a) {
    asm volatile("ldmatrix.sync.aligned.m8n8.x4.shared.b16 {%0,%1,%2,%3}, [%4];"
                 : "=r"(r[0]), "=r"(r[1]), "=r"(r[2]), "=r"(r[3]) : "r"(a));
}

static __device__ __forceinline__ void mma16816(float* c, const uint32_t* a,
                                                const uint32_t* b) {
    asm volatile(
        "mma.sync.aligned.m16n8k16.row.col.f32.f16.f16.f32 "
        "{%0,%1,%2,%3}, {%4,%5,%6,%7}, {%8,%9}, {%0,%1,%2,%3};"
        : "+f"(c[0]), "+f"(c[1]), "+f"(c[2]), "+f"(c[3])
        : "r"(a[0]), "r"(a[1]), "r"(a[2]), "r"(a[3]), "r"(b[0]), "r"(b[1]));
}

// ---------------------------------------------------------------------------
// Convert kernel: seg 0 -> x fp16, seg 1 -> W fp16. Block 0 zeroes counters.
// ---------------------------------------------------------------------------
__global__ __launch_bounds__(256) void convert_kernel(const float* __restrict__ x,
                                                      const float* __restrict__ W) {
    if (blockIdx.x == 0 && threadIdx.x < SPLIT_TILES)
        g_cnt[threadIdx.x] = 0u;
    const int half_grid = (int)(gridDim.x >> 1);
    const float* src = (blockIdx.x < half_grid) ? x : W;
    __half* dst = (blockIdx.x < half_grid) ? g_x : g_w;
    int blk = (blockIdx.x < half_grid) ? blockIdx.x : (blockIdx.x - half_grid);
    size_t i = ((size_t)blk * blockDim.x + threadIdx.x) * 8;
    float4 v0 = *reinterpret_cast<const float4*>(src + i);
    float4 v1 = *reinterpret_cast<const float4*>(src + i + 4);
    __half2 h[4];
    h[0] = __floats2half2_rn(v0.x, v0.y);
    h[1] = __floats2half2_rn(v0.z, v0.w);
    h[2] = __floats2half2_rn(v1.x, v1.y);
    h[3] = __floats2half2_rn(v1.z, v1.w);
    *reinterpret_cast<uint4*>(dst + i) = *reinterpret_cast<const uint4*>(h);
}

// ---------------------------------------------------------------------------
// Stage loader (128 threads): rows 128B wide (64 halfs); chunk cc of row r at
//   r*128 + ((cc ^ (r&7))<<4)  -> conflict-free for cp.async AND ldmatrix.
// ---------------------------------------------------------------------------
static __device__ __forceinline__ void load_stage(uint32_t sb, int stage, int kt,
                                                  int tm, int tn, int tid) {
    uint32_t st = sb + SM_TILES + stage * STAGE_BYTES;
    const uint32_t k0 = (uint32_t)kt * BK;
#pragma unroll
    for (int i = 0; i < 8; ++i) {          // A: 1024 chunks / 128 thr
        int c = i * 128 + tid;
        int r = c >> 3, cc = c & 7;
        uint32_t so = (uint32_t)r * 128 + (uint32_t)((cc ^ (r & 7)) << 4);
        cp16(st + OFF_A + so, g_x + (size_t)(tm * BM + r) * DIM + k0 + cc * 8);
    }
#pragma unroll
    for (int i = 0; i < 8; ++i) {          // B: 1024 chunks / 128 thr
        int c = i * 128 + tid;
        int r = c >> 3, cc = c & 7;
        uint32_t so = (uint32_t)r * 128 + (uint32_t)((cc ^ (r & 7)) << 4);
        cp16(st + OFF_B + so, g_w + (size_t)(tn * BN + r) * DIM + k0 + cc * 8);
    }
}

// ---------------------------------------------------------------------------
// GEMM. 4 warps @ 64x64: wm = wid&1 (2 x 64 rows), wn = wid>>1 (2 x 64 cols).
// ---------------------------------------------------------------------------
__global__ __launch_bounds__(THREADS, 2) void gemm_kernel(const float* __restrict__ bias,
                                                          float* __restrict__ out) {
    extern __shared__ __align__(1024) char smem[];
    uint32_t sb = smem_u32(smem);
    const int tid = threadIdx.x;
    const int lane = tid & 31, wid = tid >> 5;
    const int wm = wid & 1, wn = wid >> 1;

    const int pid = blockIdx.x;
    const bool split = (pid >= FULL_TILES);
    int tile, kbase, nkt, unit;
    if (!split) {
        tile = pid; kbase = 0; nkt = NKT; unit = 0;
    } else {
        unit = pid - FULL_TILES;               // 0..271, pairs adjacent
        tile = FULL_TILES + (unit >> 1);       // 888..1023
        kbase = (unit & 1) * NKT_H;
        nkt = NKT_H;
    }
    const int tm = tile & 31;
    const int tn = tile >> 5;

    reinterpret_cast<float*>(smem + SM_BIAS)[tid] = bias[tn * BN + tid];

    // per-lane ldmatrix address components (row*128 base + row-swizzle key r&7)
    uint32_t aoff[4], asw[4];
#pragma unroll
    for (int mt = 0; mt < 4; ++mt) {
        int r = wm * 64 + mt * 16 + (lane & 15);
        aoff[mt] = (uint32_t)r * 128;
        asw[mt] = (uint32_t)(r & 7);
    }
    uint32_t boff[4], bsw[4];
#pragma unroll
    for (int jj = 0; jj < 4; ++jj) {
        int r = wn * 64 + jj * 16 + ((lane >> 4) & 1) * 8 + (lane & 7);
        boff[jj] = (uint32_t)r * 128;
        bsw[jj] = (uint32_t)(r & 7);
    }
    const uint32_t cAsel = (uint32_t)(lane >> 4);        // A k-chunk select (0/1)
    const uint32_t cBsel = (uint32_t)((lane >> 3) & 1);  // B k-chunk select (0/1)

    float acc[4][8][4];
#pragma unroll
    for (int mt = 0; mt < 4; ++mt)
#pragma unroll
        for (int nt = 0; nt < 8; ++nt)
#pragma unroll
            for (int k = 0; k < 4; ++k) acc[mt][nt][k] = 0.f;

    // prologue: 2 stages in flight
    load_stage(sb, 0, kbase + 0, tm, tn, tid);
    asm volatile("cp.async.commit_group;");
    load_stage(sb, 1, kbase + 1, tm, tn, tid);
    asm volatile("cp.async.commit_group;");

    // one k-tile body at compile-time stage index; t local to this CTA's K range
    auto body = [&](int t, int sc) {
        asm volatile("cp.async.wait_group 1;");
        __syncthreads();

        if (t + 2 < nkt) {
            int sld = sc + 2; if (sld >= STAGES) sld -= STAGES;
            load_stage(sb, sld, kbase + t + 2, tm, tn, tid);
        }
        asm volatile("cp.async.commit_group;");   // empty group ok

        const uint32_t stg = sb + SM_TILES + (uint32_t)sc * STAGE_BYTES;
#pragma unroll
        for (int s = 0; s < 4; ++s) {             // four k16 steps per BK=64
            uint32_t a[4][4], b[4][4];
#pragma unroll
            for (int mt = 0; mt < 4; ++mt) {
                uint32_t ca = (uint32_t)(2 * s) + cAsel;
                ldsm4(a[mt], stg + OFF_A + aoff[mt] + ((ca ^ asw[mt]) << 4));
            }
#pragma unroll
            for (int jj = 0; jj < 4; ++jj) {
                uint32_t cb = (uint32_t)(2 * s) + cBsel;
                ldsm4(b[jj], stg + OFF_B + boff[jj] + ((cb ^ bsw[jj]) << 4));
            }
#pragma unroll
            for (int jj = 0; jj < 4; ++jj) {
                const int n0 = 2 * jj, n1 = 2 * jj + 1;
#pragma unroll
                for (int mt = 0; mt < 4; ++mt) {
                    mma16816(acc[mt][n0], a[mt], b[jj]);
                    mma16816(acc[mt][n1], a[mt], b[jj] + 2);
                }
            }
        }
    };

    // main ring: groups of 3 with compile-time stages, runtime remainder
    int tt = 0;
#pragma unroll 1
    for (; tt + 3 <= nkt; tt += 3) {
        body(tt, 0);
        body(tt + 1, 1);
        body(tt + 2, 2);
    }
    if (tt < nkt) { body(tt, 0); ++tt; }          // nkt=64: one tail (stage 0)
    if (tt < nkt) { body(tt, 1); }                // nkt=32: second tail (stage 1)

    __syncthreads();
    const float* sbias = reinterpret_cast<const float*>(smem + SM_BIAS);

    if (!split) {
        // ---- full-K epilogue: + bias, direct f32x2 stores ----
#pragma unroll
        for (int mt = 0; mt < 4; ++mt) {
#pragma unroll
            for (int nt = 0; nt < 8; ++nt) {
                int row = tm * BM + wm * 64 + mt * 16 + (lane >> 2);
                int cl = wn * 64 + nt * 8 + 2 * (lane & 3);
                float b0 = sbias[cl], b1 = sbias[cl + 1];
                float* p0 = out + (size_t)row * DIM + tn * BN + cl;
                float* p1 = p0 + 8 * DIM;
                *reinterpret_cast<float2*>(p0) =
                    make_float2(acc[mt][nt][0] + b0, acc[mt][nt][1] + b1);
                *reinterpret_cast<float2*>(p1) =
                    make_float2(acc[mt][nt][2] + b0, acc[mt][nt][3] + b1);
            }
        }
    } else {
        // ---- split-K epilogue: store partial; last arriver combines ----
        float* sp = g_part + (size_t)unit * (BM * BN);
#pragma unroll
        for (int mt = 0; mt < 4; ++mt) {
#pragma unroll
            for (int nt = 0; nt < 8; ++nt) {
                int lrow = wm * 64 + mt * 16 + (lane >> 2);
                int lcl = wn * 64 + nt * 8 + 2 * (lane & 3);
                float* q0 = sp + lrow * BN + lcl;
                float* q1 = q0 + 8 * BN;
                *reinterpret_cast<float2*>(q0) = make_float2(acc[mt][nt][0], acc[mt][nt][1]);
                *reinterpret_cast<float2*>(q1) = make_float2(acc[mt][nt][2], acc[mt][nt][3]);
            }
        }
        __threadfence();
        __syncthreads();
        if (tid == 0)
            *reinterpret_cast<unsigned*>(smem + SM_FLAG) =
                atomicAdd(&g_cnt[tile - FULL_TILES], 1u);
        __syncthreads();

        if (*reinterpret_cast<unsigned*>(smem + SM_FLAG) == 1u) {
            __threadfence();   // acquire: partner's stores visible
            const float* pp = g_part + (size_t)(unit ^ 1) * (BM * BN);
#pragma unroll
            for (int mt = 0; mt < 4; ++mt) {
#pragma unroll
                for (int nt = 0; nt < 8; ++nt) {
                    int lrow = wm * 64 + mt * 16 + (lane >> 2);
                    int lcl = wn * 64 + nt * 8 + 2 * (lane & 3);
                    float2 o0 = *reinterpret_cast<const float2*>(pp + lrow * BN + lcl);
                    float2 o1 = *reinterpret_cast<const float2*>(pp + (lrow + 8) * BN + lcl);
                    float b0 = sbias[lcl], b1 = sbias[lcl + 1];
                    int row = tm * BM + lrow;
                    float* p0 = out + (size_t)row * DIM + tn * BN + lcl;
                    float* p1 = p0 + 8 * DIM;
                    *reinterpret_cast<float2*>(p0) =
                        make_float2(acc[mt][nt][0] + o0.x + b0, acc[mt][nt][1] + o0.y + b1);
                    *reinterpret_cast<float2*>(p1) =
                        make_float2(acc[mt][nt][2] + o1.x + b0, acc[mt][nt][3] + o1.y + b1);
                }
            }
        }
    }
}

// ---------------------------------------------------------------------------
// Launch
// ---------------------------------------------------------------------------
extern "C" void kernel_launch(void* const* d_in, const int* in_sizes, int n_in,
                              void* d_out, int out_size) {
    const float* x = (const float*)d_in[0];
    const float* W = (const float*)d_in[1];
    const float* b = (const float*)d_in[2];
    float* out = (float*)d_out;

    // 2 segments x 8192 blocks (block 0 also zeroes the arrive counters)
    convert_kernel<<<16384, 256>>>(x, W);

    cudaFuncSetAttribute(gemm_kernel, cudaFuncAttributeMaxDynamicSharedMemorySize,
                         SMEM_TOTAL);
    // 888 full-K CTAs (3 packed rounds) + 272 split-K CTAs (final round)
    gemm_kernel<<<GRID_GEMM, THREADS, SMEM_TOTAL>>>(b, out);
}